// round 2
// baseline (speedup 1.0000x reference)
#include <cuda_runtime.h>
#include <cstdint>

// Shapes (fixed by the problem): B=4096, D=1024, H=4096, L=8
// out = a + x @ (V^T V) + sum_l s_l * (tanh(Z_l) @ W_l),  Z_l = x @ W_l^T + b_l
// s_l[b] = sum_h logcosh(Z_l[b,h])

#define BM 128
#define BN 128
#define BK 16
#define TM 8
#define TN 8

// Scratch (static device globals: allocation-free per harness rules)
__device__ float g_Vsq[1024 * 1024];        // 4 MB   : V^T V
__device__ float g_Z[4096 * 4096];          // 64 MB  : Z_l then tanh(Z_l), reused per l
__device__ float g_part[4096 * 32];         // 512 KB : per-(row, n-tile) logcosh partials
__device__ float g_s[4096];                 // s_l[b]

// tanh(z) and logcosh(z) from one exp:
//   e = exp(-2|z|); tanh = sign(z)*(1-e)/(1+e); logcosh = |z| + log(1+e) - ln2
__device__ __forceinline__ float tanh_lc(float z, float &lc) {
    float az = fabsf(z);
    float e  = __expf(-2.0f * az);
    float t  = __fdividef(1.0f - e, 1.0f + e);
    t = copysignf(t, z);
    lc = az + __logf(1.0f + e) - 0.6931471805599453f;
    return t;
}

// Generic tiled SGEMM.
// AT=0: A is [M,K] row-major (lda = row stride). AT=1: A is [K,M] (lda = row stride).
// BT=0: B is [K,N] row-major.                    BT=1: B is [N,K] row-major.
// EPI=0: C = acc
// EPI=1: C = acc + bias[col]
// EPI=2: C += svec[row] * acc
// EPI=3: z = acc + bias[col]; C = tanh(z); part[row][blockIdx.x] = sum_cols logcosh(z)
template<int AT, int BT, int EPI>
__global__ __launch_bounds__(256, 2)
void gemm_k(int M, int N, int K,
            const float* __restrict__ A, int lda,
            const float* __restrict__ Bp, int ldb,
            float* __restrict__ C, int ldc,
            const float* __restrict__ bias,
            const float* __restrict__ svec,
            float* __restrict__ part, int npart)
{
    __shared__ float As[BK][BM];
    __shared__ float Bs[BK][BN];

    const int tid = threadIdx.x;
    const int tx = tid & 15;        // 0..15 -> N direction
    const int ty = tid >> 4;        // 0..15 -> M direction
    const int bm = blockIdx.y * BM;
    const int bn = blockIdx.x * BN;

    float acc[TM][TN];
#pragma unroll
    for (int i = 0; i < TM; i++)
#pragma unroll
        for (int j = 0; j < TN; j++) acc[i][j] = 0.0f;

    for (int k0 = 0; k0 < K; k0 += BK) {
        // ---- load A tile into As[k][m] ----
        if (AT == 0) {
            // A[M,K] row-major: read float4 along k, scatter-transpose
            const int r = tid >> 2;              // 0..63
            const int c = (tid & 3) << 2;        // 0,4,8,12
#pragma unroll
            for (int i = 0; i < 2; i++) {
                const int row = r + i * 64;
                const float4 v = *(const float4*)(A + (size_t)(bm + row) * lda + k0 + c);
                As[c + 0][row] = v.x;
                As[c + 1][row] = v.y;
                As[c + 2][row] = v.z;
                As[c + 3][row] = v.w;
            }
        } else {
            // A[K,M]: contiguous along m, direct float4
            const int r = tid >> 5;              // 0..7
            const int c = (tid & 31) << 2;       // 0..124
#pragma unroll
            for (int i = 0; i < 2; i++) {
                const int k = r + i * 8;
                *(float4*)&As[k][c] = *(const float4*)(A + (size_t)(k0 + k) * lda + bm + c);
            }
        }
        // ---- load B tile into Bs[k][n] ----
        if (BT == 0) {
            // B[K,N] row-major: contiguous along n
            const int r = tid >> 5;
            const int c = (tid & 31) << 2;
#pragma unroll
            for (int i = 0; i < 2; i++) {
                const int k = r + i * 8;
                *(float4*)&Bs[k][c] = *(const float4*)(Bp + (size_t)(k0 + k) * ldb + bn + c);
            }
        } else {
            // B[N,K] row-major: read float4 along k, scatter-transpose
            const int r = tid >> 2;
            const int c = (tid & 3) << 2;
#pragma unroll
            for (int i = 0; i < 2; i++) {
                const int row = r + i * 64;
                const float4 v = *(const float4*)(Bp + (size_t)(bn + row) * ldb + k0 + c);
                Bs[c + 0][row] = v.x;
                Bs[c + 1][row] = v.y;
                Bs[c + 2][row] = v.z;
                Bs[c + 3][row] = v.w;
            }
        }
        __syncthreads();

#pragma unroll
        for (int k = 0; k < BK; k++) {
            float ra[TM], rb[TN];
            *(float4*)&ra[0] = *(const float4*)&As[k][ty * TM];
            *(float4*)&ra[4] = *(const float4*)&As[k][ty * TM + 4];
            *(float4*)&rb[0] = *(const float4*)&Bs[k][tx * TN];
            *(float4*)&rb[4] = *(const float4*)&Bs[k][tx * TN + 4];
#pragma unroll
            for (int i = 0; i < TM; i++)
#pragma unroll
                for (int j = 0; j < TN; j++)
                    acc[i][j] += ra[i] * rb[j];
        }
        __syncthreads();
    }

    // ---- epilogue ----
    const int col0 = bn + tx * TN;
#pragma unroll
    for (int i = 0; i < TM; i++) {
        const int row = bm + ty * TM + i;
        float* crow = C + (size_t)row * ldc + col0;

        if (EPI == 0) {
            float4 v0 = make_float4(acc[i][0], acc[i][1], acc[i][2], acc[i][3]);
            float4 v1 = make_float4(acc[i][4], acc[i][5], acc[i][6], acc[i][7]);
            *(float4*)(crow)     = v0;
            *(float4*)(crow + 4) = v1;
        } else if (EPI == 1) {
            float4 b0 = *(const float4*)(bias + col0);
            float4 b1 = *(const float4*)(bias + col0 + 4);
            float4 v0 = make_float4(acc[i][0] + b0.x, acc[i][1] + b0.y,
                                    acc[i][2] + b0.z, acc[i][3] + b0.w);
            float4 v1 = make_float4(acc[i][4] + b1.x, acc[i][5] + b1.y,
                                    acc[i][6] + b1.z, acc[i][7] + b1.w);
            *(float4*)(crow)     = v0;
            *(float4*)(crow + 4) = v1;
        } else if (EPI == 2) {
            const float sv = svec[row];
            float4 o0 = *(const float4*)(crow);
            float4 o1 = *(const float4*)(crow + 4);
            o0.x += sv * acc[i][0]; o0.y += sv * acc[i][1];
            o0.z += sv * acc[i][2]; o0.w += sv * acc[i][3];
            o1.x += sv * acc[i][4]; o1.y += sv * acc[i][5];
            o1.z += sv * acc[i][6]; o1.w += sv * acc[i][7];
            *(float4*)(crow)     = o0;
            *(float4*)(crow + 4) = o1;
        } else { // EPI == 3
            float4 b0 = *(const float4*)(bias + col0);
            float4 b1 = *(const float4*)(bias + col0 + 4);
            float zb[8];
            zb[0] = acc[i][0] + b0.x; zb[1] = acc[i][1] + b0.y;
            zb[2] = acc[i][2] + b0.z; zb[3] = acc[i][3] + b0.w;
            zb[4] = acc[i][4] + b1.x; zb[5] = acc[i][5] + b1.y;
            zb[6] = acc[i][6] + b1.z; zb[7] = acc[i][7] + b1.w;
            float lcsum = 0.0f;
            float t[8];
#pragma unroll
            for (int j = 0; j < 8; j++) {
                float lc;
                t[j] = tanh_lc(zb[j], lc);
                lcsum += lc;
            }
            *(float4*)(crow)     = make_float4(t[0], t[1], t[2], t[3]);
            *(float4*)(crow + 4) = make_float4(t[4], t[5], t[6], t[7]);
            // reduce lcsum across the 16 tx-lanes (contiguous within warp halves)
            lcsum += __shfl_xor_sync(0xffffffffu, lcsum, 1);
            lcsum += __shfl_xor_sync(0xffffffffu, lcsum, 2);
            lcsum += __shfl_xor_sync(0xffffffffu, lcsum, 4);
            lcsum += __shfl_xor_sync(0xffffffffu, lcsum, 8);
            if (tx == 0)
                part[(size_t)row * npart + blockIdx.x] = lcsum;
        }
    }
}

__global__ void reduce_partials(const float* __restrict__ part,
                                float* __restrict__ s, int np, int nrows)
{
    int b = blockIdx.x * blockDim.x + threadIdx.x;
    if (b >= nrows) return;
    float sum = 0.0f;
    for (int j = 0; j < np; j++) sum += part[(size_t)b * np + j];
    s[b] = sum;
}

extern "C" void kernel_launch(void* const* d_in, const int* in_sizes, int n_in,
                              void* d_out, int out_size)
{
    const float* x  = (const float*)d_in[0];   // [B, D]
    const float* Wk = (const float*)d_in[1];   // [L, H, D]
    const float* bk = (const float*)d_in[2];   // [L, H]
    const float* V  = (const float*)d_in[3];   // [H, D]
    const float* a  = (const float*)d_in[4];   // [D]
    float* out = (float*)d_out;                // [B, D]

    const int D = in_sizes[4];                 // 1024
    const int B = in_sizes[0] / D;             // 4096
    const int H = in_sizes[3] / D;             // 4096
    const int L = in_sizes[2] / H;             // 8

    float *pVsq, *pZ, *pPart, *pS;
    cudaGetSymbolAddress((void**)&pVsq,  g_Vsq);
    cudaGetSymbolAddress((void**)&pZ,    g_Z);
    cudaGetSymbolAddress((void**)&pPart, g_part);
    cudaGetSymbolAddress((void**)&pS,    g_s);

    const dim3 thr(256);
    const int NP = H / BN;  // 32 n-tiles per row for the Z GEMM

    // K1: Vsq = V^T V      (A = V as [K=H, M=D], B = V as [K=H, N=D])
    gemm_k<1, 0, 0><<<dim3(D / BN, D / BM), thr>>>(
        D, D, H, V, D, V, D, pVsq, D, nullptr, nullptr, nullptr, 0);

    // K2: out = a + x @ Vsq
    gemm_k<0, 0, 1><<<dim3(D / BN, B / BM), thr>>>(
        B, D, D, x, D, pVsq, D, out, D, a, nullptr, nullptr, 0);

    for (int l = 0; l < L; l++) {
        const float* Wl = Wk + (size_t)l * H * D;   // [H, D]
        const float* bl = bk + (size_t)l * H;       // [H]

        // K3: Z = x @ Wl^T + bl ; store tanh(Z) in g_Z, logcosh partials in g_part
        gemm_k<0, 1, 3><<<dim3(H / BN, B / BM), thr>>>(
            B, H, D, x, D, Wl, D, pZ, H, bl, nullptr, pPart, NP);

        // K4: s[b] = sum of partials
        reduce_partials<<<(B + 255) / 256, 256>>>(pPart, pS, NP, B);

        // K5: out += s[b] * (tanh(Z) @ Wl)
        gemm_k<0, 0, 2><<<dim3(D / BN, B / BM), thr>>>(
            B, D, H, pZ, H, Wl, D, out, D, nullptr, pS, nullptr, 0);
    }
}

// round 4
// speedup vs baseline: 2.8615x; 2.8615x over previous
#include <cuda_runtime.h>
#include <cstdint>

// Shapes: B=4096, D=1024, H=4096, L=8
// out = a + x @ (V^T V) + sum_l s_l * (tanh(Z_l) @ W_l),  Z_l = x @ W_l^T + b_l
// All GEMMs: C[M,N] = A[M,K] @ B[N,K]^T, K-major fp32 operands pre-rounded to tf32.
// Tensor path: mma.sync.m16n8k8.tf32 (plain sm_100 target — tcgen05 unavailable here).

#define BM 128
#define BN 128
#define BK 32
#define STAGES 3
#define LDS_ROW 36                      // 32 + 4 pad floats
#define ASZ_W (BM * LDS_ROW)            // 4608 words per A tile
#define STG_W (2 * ASZ_W)               // 9216 words per stage (A+B)
#define SMEM_BYTES (STAGES * STG_W * 4) // 110592

// ---------------- scratch ----------------
__device__ float g_Vsq[1024 * 1024];           // 4 MB  (tf32-rounded)
__device__ float g_VT[1024ull * 4096];         // 16 MB V^T  [D,H] rounded
__device__ float g_WkT[8ull * 1024 * 4096];    // 128 MB Wk^T [L][D,H] rounded
__device__ float g_Wr[8ull * 4096 * 1024];     // 128 MB Wk rounded [L][H,D]
__device__ float g_xr[4096ull * 1024];         // 16 MB x rounded
__device__ float g_Z[4096ull * 4096];          // 64 MB tanh(Z_l) rounded
__device__ float g_part[4096 * 128];           // 2 MB logcosh partials
__device__ float g_s[4096];

// ---------------- helpers ----------------
__device__ __forceinline__ float rna_tf32(float f) {
    uint32_t u;
    asm("cvt.rna.tf32.f32 %0, %1;" : "=r"(u) : "f"(f));
    return __uint_as_float(u);
}
__device__ __forceinline__ uint32_t cvta_s(const void* p) {
    return (uint32_t)__cvta_generic_to_shared((void*)p);
}
__device__ __forceinline__ void cp16(uint32_t s, const void* g) {
    asm volatile("cp.async.cg.shared.global [%0], [%1], 16;" :: "r"(s), "l"(g));
}
__device__ __forceinline__ void cp_commit() {
    asm volatile("cp.async.commit_group;" ::: "memory");
}
__device__ __forceinline__ void cp_wait1() {
    asm volatile("cp.async.wait_group 1;" ::: "memory");
}
__device__ __forceinline__ void mma8(float* c, const uint32_t* a, const uint32_t* b) {
    asm volatile(
        "mma.sync.aligned.m16n8k8.row.col.f32.tf32.tf32.f32 "
        "{%0,%1,%2,%3}, {%4,%5,%6,%7}, {%8,%9}, {%0,%1,%2,%3};"
        : "+f"(c[0]), "+f"(c[1]), "+f"(c[2]), "+f"(c[3])
        : "r"(a[0]), "r"(a[1]), "r"(a[2]), "r"(a[3]), "r"(b[0]), "r"(b[1]));
}
__device__ __forceinline__ float tanh_lc(float z, float &lc) {
    float az = fabsf(z);
    float e  = __expf(-2.0f * az);
    float t  = __fdividef(1.0f - e, 1.0f + e);
    t = copysignf(t, z);
    lc = az + __logf(1.0f + e) - 0.6931471805599453f;
    return t;
}

// ---------------- tf32 mma.sync GEMM ----------------
// EPI=0: C = rna_tf32(acc)                         (Vsq)
// EPI=1: C = acc + bias[col]                       (out init)
// EPI=2: C += svec[row] * acc                      (out accumulate)
// EPI=3: z = acc + bias[col]; C = rna(tanh z); part[row][bx*4+wn] = sum logcosh
template<int EPI>
__global__ void __launch_bounds__(256, 1)
mma_gemm(const float* __restrict__ A, int lda,
         const float* __restrict__ Bp, int ldb,
         int NK,
         float* __restrict__ C, int ldc,
         const float* __restrict__ bias,
         const float* __restrict__ svec,
         float* __restrict__ part, int np)
{
    extern __shared__ float smf[];
    const uint32_t sbase = cvta_s(smf);

    const int tid  = threadIdx.x;
    const int lane = tid & 31;
    const int wid  = tid >> 5;
    const int wm   = wid & 1;          // 2 warps in M (64 rows each)
    const int wn   = wid >> 1;         // 4 warps in N (32 cols each)
    const int g    = lane >> 2;        // groupID 0..7
    const int t    = lane & 3;         // thread-in-group 0..3
    const int bm   = blockIdx.y * BM;
    const int bn   = blockIdx.x * BN;

    const float* ga = A  + (size_t)bm * lda;
    const float* gb = Bp + (size_t)bn * ldb;

    // stage loader: 128 rows x 8 x 16B chunks for each of A,B
    auto load_stage = [&](int st, int kt) {
        const uint32_t sb = sbase + st * (STG_W * 4);
        const int kb = kt * BK;
#pragma unroll
        for (int i = 0; i < 4; i++) {
            int cid = tid + i * 256;
            int row = cid >> 3, kc = (cid & 7) << 2;
            cp16(sb + (row * LDS_ROW + kc) * 4,
                 ga + (size_t)row * lda + kb + kc);
        }
#pragma unroll
        for (int i = 0; i < 4; i++) {
            int cid = tid + i * 256;
            int row = cid >> 3, kc = (cid & 7) << 2;
            cp16(sb + (ASZ_W + row * LDS_ROW + kc) * 4,
                 gb + (size_t)row * ldb + kb + kc);
        }
    };

    load_stage(0, 0); cp_commit();
    load_stage(1, 1); cp_commit();

    float acc[4][4][4];
#pragma unroll
    for (int i = 0; i < 4; i++)
#pragma unroll
        for (int j = 0; j < 4; j++)
#pragma unroll
            for (int q = 0; q < 4; q++) acc[i][j][q] = 0.0f;

    const int a_off0 = (wm * 64 + g) * LDS_ROW + t;
    const int b_off0 = (wn * 32 + g) * LDS_ROW + t;

    for (int kt = 0; kt < NK; kt++) {
        cp_wait1();
        __syncthreads();
        const int kf = kt + STAGES - 1;
        if (kf < NK) load_stage(kf % STAGES, kf);
        cp_commit();

        const float* As = smf + (kt % STAGES) * STG_W;
        const float* Bs = As + ASZ_W;

#pragma unroll
        for (int ks = 0; ks < 4; ks++) {
            uint32_t af[4][4], bf[4][2];
#pragma unroll
            for (int i = 0; i < 4; i++) {
                const int o = a_off0 + i * 16 * LDS_ROW + ks * 8;
                af[i][0] = __float_as_uint(As[o]);
                af[i][1] = __float_as_uint(As[o + 8 * LDS_ROW]);
                af[i][2] = __float_as_uint(As[o + 4]);
                af[i][3] = __float_as_uint(As[o + 8 * LDS_ROW + 4]);
            }
#pragma unroll
            for (int j = 0; j < 4; j++) {
                const int o = b_off0 + j * 8 * LDS_ROW + ks * 8;
                bf[j][0] = __float_as_uint(Bs[o]);
                bf[j][1] = __float_as_uint(Bs[o + 4]);
            }
#pragma unroll
            for (int i = 0; i < 4; i++)
#pragma unroll
                for (int j = 0; j < 4; j++)
                    mma8(acc[i][j], af[i], bf[j]);
        }
    }

    // ---------------- epilogue ----------------
    float lc0[4], lc1[4];
#pragma unroll
    for (int i = 0; i < 4; i++) { lc0[i] = 0.0f; lc1[i] = 0.0f; }

#pragma unroll
    for (int i = 0; i < 4; i++) {
        const int row0 = bm + wm * 64 + i * 16 + g;
        const int row1 = row0 + 8;
        float sv0 = 0.0f, sv1 = 0.0f;
        if (EPI == 2) { sv0 = svec[row0]; sv1 = svec[row1]; }
#pragma unroll
        for (int j = 0; j < 4; j++) {
            const int col = bn + wn * 32 + j * 8 + 2 * t;
            float2* p0 = (float2*)(C + (size_t)row0 * ldc + col);
            float2* p1 = (float2*)(C + (size_t)row1 * ldc + col);
            float a0 = acc[i][j][0], a1 = acc[i][j][1];
            float a2 = acc[i][j][2], a3 = acc[i][j][3];
            if (EPI == 0) {
                *p0 = make_float2(rna_tf32(a0), rna_tf32(a1));
                *p1 = make_float2(rna_tf32(a2), rna_tf32(a3));
            } else if (EPI == 1) {
                const float b0 = bias[col], b1 = bias[col + 1];
                *p0 = make_float2(a0 + b0, a1 + b1);
                *p1 = make_float2(a2 + b0, a3 + b1);
            } else if (EPI == 2) {
                float2 o0 = *p0, o1 = *p1;
                o0.x += sv0 * a0; o0.y += sv0 * a1;
                o1.x += sv1 * a2; o1.y += sv1 * a3;
                *p0 = o0; *p1 = o1;
            } else {
                const float b0 = bias[col], b1 = bias[col + 1];
                float lc;
                float t0 = tanh_lc(a0 + b0, lc); lc0[i] += lc;
                float t1 = tanh_lc(a1 + b1, lc); lc0[i] += lc;
                float t2 = tanh_lc(a2 + b0, lc); lc1[i] += lc;
                float t3 = tanh_lc(a3 + b1, lc); lc1[i] += lc;
                *p0 = make_float2(rna_tf32(t0), rna_tf32(t1));
                *p1 = make_float2(rna_tf32(t2), rna_tf32(t3));
            }
        }
    }

    if (EPI == 3) {
        const int chunk = blockIdx.x * 4 + wn;
#pragma unroll
        for (int i = 0; i < 4; i++) {
            lc0[i] += __shfl_xor_sync(0xffffffffu, lc0[i], 1);
            lc0[i] += __shfl_xor_sync(0xffffffffu, lc0[i], 2);
            lc1[i] += __shfl_xor_sync(0xffffffffu, lc1[i], 1);
            lc1[i] += __shfl_xor_sync(0xffffffffu, lc1[i], 2);
        }
        if (t == 0) {
#pragma unroll
            for (int i = 0; i < 4; i++) {
                const int row0 = bm + wm * 64 + i * 16 + g;
                part[(size_t)row0 * np + chunk]       = lc0[i];
                part[(size_t)(row0 + 8) * np + chunk] = lc1[i];
            }
        }
    }
}

// ---------------- prep kernels ----------------
__global__ void __launch_bounds__(256)
round_copy(const float* __restrict__ in, float* __restrict__ out, size_t n4)
{
    size_t i = (size_t)blockIdx.x * blockDim.x + threadIdx.x;
    if (i >= n4) return;
    float4 v = ((const float4*)in)[i];
    v.x = rna_tf32(v.x); v.y = rna_tf32(v.y);
    v.z = rna_tf32(v.z); v.w = rna_tf32(v.w);
    ((float4*)out)[i] = v;
}

// in[R,C] -> out[C,R], rounded, per z-layer
__global__ void __launch_bounds__(256)
transpose_k(const float* __restrict__ in, float* __restrict__ out, int R, int C)
{
    __shared__ float t[32][33];
    const size_t lz = (size_t)blockIdx.z * R * C;
    in += lz; out += lz;
    const int r0 = blockIdx.y * 32, c0 = blockIdx.x * 32;
    const int tx = threadIdx.x, ty = threadIdx.y;
#pragma unroll
    for (int i = 0; i < 32; i += 8)
        t[ty + i][tx] = rna_tf32(in[(size_t)(r0 + ty + i) * C + c0 + tx]);
    __syncthreads();
#pragma unroll
    for (int i = 0; i < 32; i += 8)
        out[(size_t)(c0 + ty + i) * R + r0 + tx] = t[tx][ty + i];
}

__global__ void reduce_partials(const float* __restrict__ part,
                                float* __restrict__ s, int np, int nrows)
{
    int b = blockIdx.x * blockDim.x + threadIdx.x;
    if (b >= nrows) return;
    float sum = 0.0f;
    for (int j = 0; j < np; j++) sum += part[(size_t)b * np + j];
    s[b] = sum;
}

// ---------------- host ----------------
extern "C" void kernel_launch(void* const* d_in, const int* in_sizes, int n_in,
                              void* d_out, int out_size)
{
    const float* x  = (const float*)d_in[0];   // [B, D]
    const float* Wk = (const float*)d_in[1];   // [L, H, D]
    const float* bk = (const float*)d_in[2];   // [L, H]
    const float* V  = (const float*)d_in[3];   // [H, D]
    const float* a  = (const float*)d_in[4];   // [D]
    float* out = (float*)d_out;                // [B, D]

    const int D = in_sizes[4];                 // 1024
    const int B = in_sizes[0] / D;             // 4096
    const int H = in_sizes[3] / D;             // 4096
    const int L = in_sizes[2] / H;             // 8

    float *pVsq, *pVT, *pWkT, *pWr, *pXr, *pZ, *pPart, *pS;
    cudaGetSymbolAddress((void**)&pVsq,  g_Vsq);
    cudaGetSymbolAddress((void**)&pVT,   g_VT);
    cudaGetSymbolAddress((void**)&pWkT,  g_WkT);
    cudaGetSymbolAddress((void**)&pWr,   g_Wr);
    cudaGetSymbolAddress((void**)&pXr,   g_xr);
    cudaGetSymbolAddress((void**)&pZ,    g_Z);
    cudaGetSymbolAddress((void**)&pPart, g_part);
    cudaGetSymbolAddress((void**)&pS,    g_s);

    cudaFuncSetAttribute(mma_gemm<0>, cudaFuncAttributeMaxDynamicSharedMemorySize, SMEM_BYTES);
    cudaFuncSetAttribute(mma_gemm<1>, cudaFuncAttributeMaxDynamicSharedMemorySize, SMEM_BYTES);
    cudaFuncSetAttribute(mma_gemm<2>, cudaFuncAttributeMaxDynamicSharedMemorySize, SMEM_BYTES);
    cudaFuncSetAttribute(mma_gemm<3>, cudaFuncAttributeMaxDynamicSharedMemorySize, SMEM_BYTES);

    // prep: rounded copies + rounded transposes
    {
        size_t n4 = (size_t)B * D / 4;
        round_copy<<<(unsigned)((n4 + 255) / 256), 256>>>(x, pXr, n4);
        n4 = (size_t)L * H * D / 4;
        round_copy<<<(unsigned)((n4 + 255) / 256), 256>>>(Wk, pWr, n4);
    }
    transpose_k<<<dim3(D / 32, H / 32, 1), dim3(32, 8)>>>(V,  pVT,  H, D);
    transpose_k<<<dim3(D / 32, H / 32, L), dim3(32, 8)>>>(Wk, pWkT, H, D);

    // K1: Vsq = VT @ VT^T  (A = VT[D,H], B = VT[D,H]) — store rounded
    mma_gemm<0><<<dim3(D / BN, D / BM), 256, SMEM_BYTES>>>(
        pVT, H, pVT, H, H / BK, pVsq, D, nullptr, nullptr, nullptr, 0);

    // K2: out = a + x @ Vsq   (Vsq symmetric → valid as [N,K])
    mma_gemm<1><<<dim3(D / BN, B / BM), 256, SMEM_BYTES>>>(
        pXr, D, pVsq, D, D / BK, out, D, a, nullptr, nullptr, 0);

    const int NP = (H / BN) * 4;   // 128
    for (int l = 0; l < L; l++) {
        // K3: Z = x @ Wl^T + bl ; g_Z = rna(tanh Z), logcosh partials
        mma_gemm<3><<<dim3(H / BN, B / BM), 256, SMEM_BYTES>>>(
            pXr, D, pWr + (size_t)l * H * D, D, D / BK,
            pZ, H, bk + (size_t)l * H, nullptr, pPart, NP);

        reduce_partials<<<(B + 255) / 256, 256>>>(pPart, pS, NP, B);

        // K5: out += s[b] * (tanh(Z) @ Wl)  (B = WkT[l] as [D,H])
        mma_gemm<2><<<dim3(D / BN, B / BM), 256, SMEM_BYTES>>>(
            pZ, H, pWkT + (size_t)l * D * H, H, H / BK,
            out, D, nullptr, pS, nullptr, 0);
    }
}